// round 13
// baseline (speedup 1.0000x reference)
#include <cuda_runtime.h>
#include <cuda_bf16.h>
#include <cstdint>

// ---------------- Problem constants ----------------
#define NB      64
#define NNODES  512
#define NV      64
#define HD      256
#define IN_DIM  128
#define OUT_DIM 10
#define TOTAL_N (NB * NNODES)        // 32768
#define EDGES   (NB * 16384)         // 1048576
#define CSR_CAP 128

// ---------------- Scratch ----------------
__device__ int   g_cnt[TOTAL_N];
__device__ float g_dinv[TOTAL_N];
__device__ int   g_csr[(long)TOTAL_N * CSR_CAP];
__device__ float g_wc[IN_DIM * HD];
__device__ float g_bc[HD];
__device__ float g_y[(long)TOTAL_N * IN_DIM];
__device__ float g_sc[TOTAL_N];
__device__ float g_g[(long)TOTAL_N * HD];
__device__ float g_t1[(long)TOTAL_N * HD];
__device__ float g_t[(long)TOTAL_N * HD];
__device__ float g_proto[NB * HD];
__device__ float g_pn[NB];
__device__ float g_ct[(long)NB * NV * NNODES];
__device__ float g_vn[(long)NB * NV * HD];
__device__ float g_vnr[(long)NB * NV * HD];
__device__ float g_vn2[(long)NB * NV * HD];

// ---------------- helpers ----------------
__device__ __forceinline__ float warp_sum(float v) {
    #pragma unroll
    for (int o = 16; o > 0; o >>= 1) v += __shfl_xor_sync(0xffffffff, v, o);
    return v;
}

__global__ void cnt_zero_kernel(int* __restrict__ cnt) {
    int i = blockIdx.x * blockDim.x + threadIdx.x;
    if (i < TOTAL_N) cnt[i] = 0;
}

__global__ void csr_fill_kernel(const int* __restrict__ src, const int* __restrict__ dst,
                                int* __restrict__ cnt, int* __restrict__ csr) {
    int e = blockIdx.x * blockDim.x + threadIdx.x;
    if (e >= EDGES) return;
    int s = src[e], d = dst[e];
    int pos = atomicAdd(&cnt[d], 1);
    if (pos < CSR_CAP) csr[(long)d * CSR_CAP + pos] = s;
}

__global__ void dinv_kernel(const int* __restrict__ cnt, float* __restrict__ dinv) {
    int i = blockIdx.x * blockDim.x + threadIdx.x;
    if (i < TOTAL_N) dinv[i] = rsqrtf(1.0f + (float)cnt[i]);
}

// ---------------- weight fold: block-internal split-K ----------------
__global__ __launch_bounds__(1024) void fold4_kernel(
    const float* __restrict__ W_emb, const float* __restrict__ b_emb,
    const float* __restrict__ W_gcn,
    float* __restrict__ wc, float* __restrict__ bc)
{
    __shared__ float sa[HD];
    __shared__ float pacc[4][HD];
    const int tid = threadIdx.x;
    const int ks = tid >> 8;
    const int c  = tid & 255;
    const int r  = blockIdx.x;

    if (tid < HD) sa[tid] = (r < IN_DIM) ? W_emb[(long)r * HD + tid] : b_emb[tid];
    __syncthreads();

    const int k0 = ks * 64;
    float acc = 0.f;
    #pragma unroll 8
    for (int k = 0; k < 64; k++)
        acc += sa[k0 + k] * W_gcn[(long)(k0 + k) * HD + c];
    pacc[ks][c] = acc;
    __syncthreads();

    if (ks == 0) {
        float tot = pacc[0][c] + pacc[1][c] + pacc[2][c] + pacc[3][c];
        if (r < IN_DIM) wc[(long)r * HD + c] = tot;
        else            bc[c] = tot;
    }
}

// ---------------- smem-resident gather: one CTA per (graph, feature-half) ----------------
// smem holds x[b][:, half*64 : half*64+64] = 512 rows x 64 floats = 128 KB.
// All edge gathers for graph b read rows from smem instead of L2.
#define GATHER_SMEM (NNODES * 64 * 4)   // 131072 B

__global__ __launch_bounds__(512) void gcn_gather_smem(
    const int* __restrict__ cnt, const int* __restrict__ csr,
    const float* __restrict__ dinv, const float4* __restrict__ x4,
    float* __restrict__ y, float* __restrict__ sc)
{
    extern __shared__ float sx[];        // [512][64]
    const int b    = blockIdx.x;
    const int half = blockIdx.y;
    const int tid  = threadIdx.x;
    const int wid  = tid >> 5, lane = tid & 31;

    // stage the feature-half: 512 rows x 16 float4 (coalesced 256B chunks per row)
    const float4* xb = x4 + (long)b * NNODES * 32 + half * 16;
    float4* sx4 = reinterpret_cast<float4*>(sx);
    #pragma unroll
    for (int i = tid; i < NNODES * 16; i += 512) {
        int row = i >> 4, q = i & 15;
        sx4[row * 16 + q] = xb[(long)row * 32 + q];
    }
    __syncthreads();

    // 16 warps x 32 nodes each
    for (int i = 0; i < NNODES / 16; i++) {
        int nl   = wid + 16 * i;
        int node = b * NNODES + nl;
        int mr = cnt[node];
        int m  = mr > CSR_CAP ? CSR_CAP : mr;
        long base = (long)node * CSR_CAP;

        float inv = 1.0f / (1.0f + (float)mr);
        float rsd = dinv[node];

        float2 a = *reinterpret_cast<const float2*>(&sx[nl * 64 + lane * 2]);
        float accx = a.x * inv, accy = a.y * inv;
        float cs = inv;

        int e = 0;
        for (; e + 4 <= m; e += 4) {
            int s0 = csr[base + e + 0], s1 = csr[base + e + 1];
            int s2 = csr[base + e + 2], s3 = csr[base + e + 3];
            float c0 = dinv[s0] * rsd, c1 = dinv[s1] * rsd;
            float c2 = dinv[s2] * rsd, c3 = dinv[s3] * rsd;
            float2 v0 = *reinterpret_cast<const float2*>(&sx[(s0 & 511) * 64 + lane * 2]);
            float2 v1 = *reinterpret_cast<const float2*>(&sx[(s1 & 511) * 64 + lane * 2]);
            float2 v2 = *reinterpret_cast<const float2*>(&sx[(s2 & 511) * 64 + lane * 2]);
            float2 v3 = *reinterpret_cast<const float2*>(&sx[(s3 & 511) * 64 + lane * 2]);
            accx += c0 * v0.x + c1 * v1.x + c2 * v2.x + c3 * v3.x;
            accy += c0 * v0.y + c1 * v1.y + c2 * v2.y + c3 * v3.y;
            cs += c0 + c1 + c2 + c3;
        }
        for (; e < m; e++) {
            int s0 = csr[base + e];
            float cc = dinv[s0] * rsd;
            float2 v = *reinterpret_cast<const float2*>(&sx[(s0 & 511) * 64 + lane * 2]);
            accx += cc * v.x; accy += cc * v.y;
            cs += cc;
        }

        *reinterpret_cast<float2*>(&y[(long)node * IN_DIM + half * 64 + lane * 2]) =
            make_float2(accx, accy);
        if (half == 0 && lane == 0) sc[node] = cs;
    }
}

// ---------------- 3xTF32 tensor-core GEMM (fp32-accurate) ----------------
__device__ __forceinline__ void mma_tf32(float* d, const uint32_t* a, const uint32_t* b) {
    asm volatile(
        "mma.sync.aligned.m16n8k8.row.col.f32.tf32.tf32.f32 "
        "{%0,%1,%2,%3}, {%4,%5,%6,%7}, {%8,%9}, {%0,%1,%2,%3};\n"
        : "+f"(d[0]), "+f"(d[1]), "+f"(d[2]), "+f"(d[3])
        : "r"(a[0]), "r"(a[1]), "r"(a[2]), "r"(a[3]), "r"(b[0]), "r"(b[1]));
}

__device__ __forceinline__ void split_tf32(float v, uint32_t& hi, uint32_t& lo) {
    uint32_t h;
    asm("cvt.rna.tf32.f32 %0, %1;" : "=r"(h) : "f"(v));
    float l = v - __uint_as_float(h);
    uint32_t lw;
    asm("cvt.rna.tf32.f32 %0, %1;" : "=r"(lw) : "f"(l));
    hi = h; lo = lw;
}

#define TBM 128
#define TBN 128
#define TBK 32
#define ASTRIDE (TBK + 4)
#define BSTRIDE (TBN + 4)

__global__ __launch_bounds__(256) void tf32x3_gemm(
    const float* __restrict__ A, const float* __restrict__ B,
    const float* __restrict__ bias, float* __restrict__ C,
    int M, int N, int K, int hasBias, int relu,
    const float* __restrict__ rowScale, const float* __restrict__ bias2, int hasRS)
{
    __shared__ float As[TBM * ASTRIDE];
    __shared__ float Bs[TBK * BSTRIDE];

    const int tid  = threadIdx.x;
    const int wid  = tid >> 5, lane = tid & 31;
    const int warpM = wid & 1;
    const int warpN = wid >> 1;
    const int grp = lane >> 2, tig = lane & 3;

    const int blockRow = blockIdx.y * TBM;
    const int blockCol = blockIdx.x * TBN;

    const int aRow  = tid >> 3;
    const int aCol  = (tid & 7) * 4;
    const int bRow8 = tid >> 5;
    const int bCol4 = (tid & 31) * 4;

    float acc[4][4][4];
    #pragma unroll
    for (int i = 0; i < 4; i++)
        #pragma unroll
        for (int j = 0; j < 4; j++)
            #pragma unroll
            for (int r = 0; r < 4; r++) acc[i][j][r] = 0.f;

    for (int bk = 0; bk < K; bk += TBK) {
        #pragma unroll
        for (int rr = 0; rr < 4; rr++) {
            int r = aRow + 32 * rr;
            float4 a4 = *reinterpret_cast<const float4*>(
                A + (long)(blockRow + r) * K + bk + aCol);
            *reinterpret_cast<float4*>(&As[r * ASTRIDE + aCol]) = a4;
            int rb = bRow8 + 8 * rr;
            float4 b4 = *reinterpret_cast<const float4*>(
                B + (long)(bk + rb) * N + blockCol + bCol4);
            *reinterpret_cast<float4*>(&Bs[rb * BSTRIDE + bCol4]) = b4;
        }
        __syncthreads();

        #pragma unroll
        for (int kk = 0; kk < TBK; kk += 8) {
            uint32_t ah[4][4], al[4][4];
            #pragma unroll
            for (int mi = 0; mi < 4; mi++) {
                int r0 = warpM * 64 + mi * 16 + grp;
                split_tf32(As[(r0    ) * ASTRIDE + kk + tig    ], ah[mi][0], al[mi][0]);
                split_tf32(As[(r0 + 8) * ASTRIDE + kk + tig    ], ah[mi][1], al[mi][1]);
                split_tf32(As[(r0    ) * ASTRIDE + kk + tig + 4], ah[mi][2], al[mi][2]);
                split_tf32(As[(r0 + 8) * ASTRIDE + kk + tig + 4], ah[mi][3], al[mi][3]);
            }
            uint32_t bh[4][2], bl[4][2];
            #pragma unroll
            for (int ni = 0; ni < 4; ni++) {
                int c0 = warpN * 32 + ni * 8 + grp;
                split_tf32(Bs[(kk + tig    ) * BSTRIDE + c0], bh[ni][0], bl[ni][0]);
                split_tf32(Bs[(kk + tig + 4) * BSTRIDE + c0], bh[ni][1], bl[ni][1]);
            }
            #pragma unroll
            for (int mi = 0; mi < 4; mi++)
                #pragma unroll
                for (int ni = 0; ni < 4; ni++) {
                    mma_tf32(acc[mi][ni], al[mi], bh[ni]);
                    mma_tf32(acc[mi][ni], ah[mi], bl[ni]);
                    mma_tf32(acc[mi][ni], ah[mi], bh[ni]);
                }
        }
        __syncthreads();
    }

    #pragma unroll
    for (int mi = 0; mi < 4; mi++) {
        int row = blockRow + warpM * 64 + mi * 16 + grp;
        float rs0 = 0.f, rs1 = 0.f;
        if (hasRS) { rs0 = rowScale[row]; rs1 = rowScale[row + 8]; }
        #pragma unroll
        for (int ni = 0; ni < 4; ni++) {
            int col = blockCol + warpN * 32 + ni * 8 + 2 * tig;
            float2 bv = make_float2(0.f, 0.f);
            if (hasBias) bv = *reinterpret_cast<const float2*>(&bias[col]);
            float2 b2 = make_float2(0.f, 0.f);
            if (hasRS) b2 = *reinterpret_cast<const float2*>(&bias2[col]);
            float2 o0 = make_float2(acc[mi][ni][0] + bv.x + rs0 * b2.x,
                                    acc[mi][ni][1] + bv.y + rs0 * b2.y);
            float2 o1 = make_float2(acc[mi][ni][2] + bv.x + rs1 * b2.x,
                                    acc[mi][ni][3] + bv.y + rs1 * b2.y);
            if (relu) {
                o0.x = fmaxf(o0.x, 0.f); o0.y = fmaxf(o0.y, 0.f);
                o1.x = fmaxf(o1.x, 0.f); o1.y = fmaxf(o1.y, 0.f);
            }
            *reinterpret_cast<float2*>(&C[(long)row * N + col])       = o0;
            *reinterpret_cast<float2*>(&C[(long)(row + 8) * N + col]) = o1;
        }
    }
}

// ---------------- batched 3xTF32 GEMM for vn ----------------
__global__ __launch_bounds__(256) void vn_gemm(
    const float* __restrict__ Am, const float* __restrict__ Bm, float* __restrict__ Cm)
{
    __shared__ float As[NV * ASTRIDE];
    __shared__ float Bs[TBK * BSTRIDE];

    const int tid  = threadIdx.x;
    const int wid  = tid >> 5, lane = tid & 31;
    const int warpM = wid & 1;
    const int warpN = wid >> 1;
    const int grp = lane >> 2, tig = lane & 3;

    const int z = blockIdx.z;
    const float* A = Am + (long)z * NV * NNODES;
    const float* B = Bm + (long)z * NNODES * HD;
    float*       C = Cm + (long)z * NV * HD;
    const int blockCol = blockIdx.x * TBN;

    const int aRow  = tid >> 3;
    const int aCol  = (tid & 7) * 4;
    const int bRow8 = tid >> 5;
    const int bCol4 = (tid & 31) * 4;

    float acc[2][4][4];
    #pragma unroll
    for (int i = 0; i < 2; i++)
        #pragma unroll
        for (int j = 0; j < 4; j++)
            #pragma unroll
            for (int r = 0; r < 4; r++) acc[i][j][r] = 0.f;

    for (int bk = 0; bk < NNODES; bk += TBK) {
        #pragma unroll
        for (int rr = 0; rr < 2; rr++) {
            int r = aRow + 32 * rr;
            float4 a4 = *reinterpret_cast<const float4*>(A + (long)r * NNODES + bk + aCol);
            *reinterpret_cast<float4*>(&As[r * ASTRIDE + aCol]) = a4;
        }
        #pragma unroll
        for (int rr = 0; rr < 4; rr++) {
            int rb = bRow8 + 8 * rr;
            float4 b4 = *reinterpret_cast<const float4*>(B + (long)(bk + rb) * HD + blockCol + bCol4);
            *reinterpret_cast<float4*>(&Bs[rb * BSTRIDE + bCol4]) = b4;
        }
        __syncthreads();

        #pragma unroll
        for (int kk = 0; kk < TBK; kk += 8) {
            uint32_t ah[2][4], al[2][4];
            #pragma unroll
            for (int mi = 0; mi < 2; mi++) {
                int r0 = warpM * 32 + mi * 16 + grp;
                split_tf32(As[(r0    ) * ASTRIDE + kk + tig    ], ah[mi][0], al[mi][0]);
                split_tf32(As[(r0 + 8) * ASTRIDE + kk + tig    ], ah[mi][1], al[mi][1]);
                split_tf32(As[(r0    ) * ASTRIDE + kk + tig + 4], ah[mi][2], al[mi][2]);
                split_tf32(As[(r0 + 8) * ASTRIDE + kk + tig + 4], ah[mi][3], al[mi][3]);
            }
            uint32_t bh[4][2], bl[4][2];
            #pragma unroll
            for (int ni = 0; ni < 4; ni++) {
                int c0 = warpN * 32 + ni * 8 + grp;
                split_tf32(Bs[(kk + tig    ) * BSTRIDE + c0], bh[ni][0], bl[ni][0]);
                split_tf32(Bs[(kk + tig + 4) * BSTRIDE + c0], bh[ni][1], bl[ni][1]);
            }
            #pragma unroll
            for (int mi = 0; mi < 2; mi++)
                #pragma unroll
                for (int ni = 0; ni < 4; ni++) {
                    mma_tf32(acc[mi][ni], al[mi], bh[ni]);
                    mma_tf32(acc[mi][ni], ah[mi], bl[ni]);
                    mma_tf32(acc[mi][ni], ah[mi], bh[ni]);
                }
        }
        __syncthreads();
    }

    #pragma unroll
    for (int mi = 0; mi < 2; mi++) {
        int row = warpM * 32 + mi * 16 + grp;
        #pragma unroll
        for (int ni = 0; ni < 4; ni++) {
            int col = blockCol + warpN * 32 + ni * 8 + 2 * tig;
            *reinterpret_cast<float2*>(&C[(long)row * HD + col]) =
                make_float2(acc[mi][ni][0], acc[mi][ni][1]);
            *reinterpret_cast<float2*>(&C[(long)(row + 8) * HD + col]) =
                make_float2(acc[mi][ni][2], acc[mi][ni][3]);
        }
    }
}

// ---------------- proto mean + norm (fused) ----------------
__global__ void proto_pn_kernel(const float* __restrict__ t, float* __restrict__ proto,
                                float* __restrict__ pn) {
    int b = blockIdx.x, h = threadIdx.x;
    const float* tb = t + (long)b * NNODES * HD + h;
    float s = 0.f;
    #pragma unroll 4
    for (int n = 0; n < NNODES; n++) s += tb[(long)n * HD];
    float p = s * (1.0f / NNODES);
    proto[b * HD + h] = p;
    __shared__ float red[8];
    float sq = warp_sum(p * p);
    if ((h & 31) == 0) red[h >> 5] = sq;
    __syncthreads();
    if (h == 0) {
        float tot = 0.f;
        #pragma unroll
        for (int i = 0; i < 8; i++) tot += red[i];
        pn[b] = fmaxf(sqrtf(tot), 1e-8f);
    }
}

// ---------------- fused attention + row-normalized mw (writes TRANSPOSED c) ----------------
__global__ void att_mw_kernel(const float* __restrict__ t, const float* __restrict__ proto,
                              const float* __restrict__ pn, const float* __restrict__ ew,
                              float* __restrict__ ct) {
    int warp = (blockIdx.x * blockDim.x + threadIdx.x) >> 5;
    int lane = threadIdx.x & 31;
    if (warp >= TOTAL_N) return;
    int b  = warp >> 9;
    int nl = warp & 511;
    const float* tr = t + (long)warp * HD;
    const float* pr = proto + b * HD;
    float s2 = 0.f, dp = 0.f;
    #pragma unroll
    for (int h = lane; h < HD; h += 32) {
        float tv = tr[h];
        s2 += tv * tv;
        dp += tv * pr[h];
    }
    s2 = warp_sum(s2);
    dp = warp_sum(dp);
    float tn = fmaxf(sqrtf(s2), 1e-8f);
    float a  = 0.5f * (1.0f + dp / (tn * pn[b]));

    const float* er = ew + (long)warp * NV;
    float m0 = er[lane]      * a;
    float m1 = er[lane + 32] * a;
    float rs = warp_sum(m0 + m1);
    float d  = (rs == 0.f) ? 1.f : rs;
    ct[((long)b * NV + lane)      * NNODES + nl] = m0 / d;
    ct[((long)b * NV + lane + 32) * NNODES + nl] = m1 / d;
}

// ---------------- fused tail: gf mean + MLP1 + out ----------------
__global__ void tail_kernel(const float* __restrict__ vn2,
                            const float* __restrict__ mW1, const float* __restrict__ mb1,
                            const float* __restrict__ mW2, const float* __restrict__ mb2,
                            float* __restrict__ out) {
    int b = blockIdx.x, h = threadIdx.x;
    __shared__ float sgf[HD];
    __shared__ float sm1[HD];

    float s = 0.f;
    #pragma unroll 4
    for (int v = 0; v < NV; v++) s += vn2[((long)b * NV + v) * HD + h];
    sgf[h] = s * (1.0f / NV);
    __syncthreads();

    float acc = 0.f;
    #pragma unroll 4
    for (int k = 0; k < HD; k++) acc += sgf[k] * mW1[(long)k * HD + h];
    sm1[h] = fmaxf(acc + mb1[h], 0.f);
    __syncthreads();

    if (h < OUT_DIM) {
        float a2 = 0.f;
        #pragma unroll 4
        for (int k = 0; k < HD; k++) a2 += sm1[k] * mW2[(long)k * OUT_DIM + h];
        out[b * OUT_DIM + h] = a2 + mb2[h];
    }
}

// ---------------- launch ----------------
extern "C" void kernel_launch(void* const* d_in, const int* in_sizes, int n_in,
                              void* d_out, int out_size) {
    const float* x     = (const float*)d_in[0];
    const int*   esrc  = (const int*)  d_in[1];
    const int*   edst  = (const int*)  d_in[2];
    const float* W_emb = (const float*)d_in[3];
    const float* b_emb = (const float*)d_in[4];
    const float* W_gcn = (const float*)d_in[5];
    const float* b_gcn = (const float*)d_in[6];
    const float* aW1   = (const float*)d_in[7];
    const float* ab1   = (const float*)d_in[8];
    const float* aW2   = (const float*)d_in[9];
    const float* ab2   = (const float*)d_in[10];
    const float* vW1   = (const float*)d_in[11];
    const float* vb1   = (const float*)d_in[12];
    const float* vW2   = (const float*)d_in[13];
    const float* vb2   = (const float*)d_in[14];
    const float* mW1   = (const float*)d_in[15];
    const float* mb1   = (const float*)d_in[16];
    const float* mW2   = (const float*)d_in[17];
    const float* mb2   = (const float*)d_in[18];
    const float* ew    = (const float*)d_in[19];
    float* out = (float*)d_out;

    float *d_dinv, *d_wc, *d_bc, *d_y, *d_sc, *d_g, *d_t1, *d_t, *d_proto, *d_pn,
          *d_ct, *d_vn, *d_vnr, *d_vn2;
    int *d_cnt, *d_csr;
    cudaGetSymbolAddress((void**)&d_cnt,   g_cnt);
    cudaGetSymbolAddress((void**)&d_dinv,  g_dinv);
    cudaGetSymbolAddress((void**)&d_csr,   g_csr);
    cudaGetSymbolAddress((void**)&d_wc,    g_wc);
    cudaGetSymbolAddress((void**)&d_bc,    g_bc);
    cudaGetSymbolAddress((void**)&d_y,     g_y);
    cudaGetSymbolAddress((void**)&d_sc,    g_sc);
    cudaGetSymbolAddress((void**)&d_g,     g_g);
    cudaGetSymbolAddress((void**)&d_t1,    g_t1);
    cudaGetSymbolAddress((void**)&d_t,     g_t);
    cudaGetSymbolAddress((void**)&d_proto, g_proto);
    cudaGetSymbolAddress((void**)&d_pn,    g_pn);
    cudaGetSymbolAddress((void**)&d_ct,    g_ct);
    cudaGetSymbolAddress((void**)&d_vn,    g_vn);
    cudaGetSymbolAddress((void**)&d_vnr,   g_vnr);
    cudaGetSymbolAddress((void**)&d_vn2,   g_vn2);

    static int smem_set = 0;
    if (!smem_set) {
        cudaFuncSetAttribute(gcn_gather_smem,
                             cudaFuncAttributeMaxDynamicSharedMemorySize, GATHER_SMEM);
        smem_set = 1;
    }

    // CSR build (counts double as degrees)
    cnt_zero_kernel<<<TOTAL_N / 256, 256>>>(d_cnt);
    csr_fill_kernel<<<EDGES / 256, 256>>>(esrc, edst, d_cnt, d_csr);
    dinv_kernel<<<TOTAL_N / 256, 256>>>(d_cnt, d_dinv);

    // weight fold (block-internal split-K)
    fold4_kernel<<<IN_DIM + 1, 1024>>>(W_emb, b_emb, W_gcn, d_wc, d_bc);

    // sparse aggregation in x-space, x staged in smem per (graph, half)
    gcn_gather_smem<<<dim3(NB, 2), 512, GATHER_SMEM>>>(
        d_cnt, d_csr, d_dinv, (const float4*)x, d_y, d_sc);

    // g = relu(y @ Wc + sc*bc + b_gcn)
    tf32x3_gemm<<<dim3(HD / TBN, TOTAL_N / TBM), 256>>>(
        d_y, d_wc, b_gcn, d_g, TOTAL_N, HD, IN_DIM, 1, 1, d_sc, d_bc, 1);

    // affinity MLP
    tf32x3_gemm<<<dim3(HD / TBN, TOTAL_N / TBM), 256>>>(
        d_g, aW1, ab1, d_t1, TOTAL_N, HD, HD, 1, 1, nullptr, nullptr, 0);
    tf32x3_gemm<<<dim3(HD / TBN, TOTAL_N / TBM), 256>>>(
        d_t1, aW2, ab2, d_t, TOTAL_N, HD, HD, 1, 0, nullptr, nullptr, 0);

    proto_pn_kernel<<<NB, HD>>>(d_t, d_proto, d_pn);
    att_mw_kernel<<<TOTAL_N / 8, 256>>>(d_t, d_proto, d_pn, ew, d_ct);

    // vn[b] = ct[b] @ g[b]
    vn_gemm<<<dim3(HD / TBN, 1, NB), 256>>>(d_ct, d_g, d_vn);

    // virtual-node MLP
    tf32x3_gemm<<<dim3(HD / TBN, (NB * NV) / TBM), 256>>>(
        d_vn, vW1, vb1, d_vnr, NB * NV, HD, HD, 1, 1, nullptr, nullptr, 0);
    tf32x3_gemm<<<dim3(HD / TBN, (NB * NV) / TBM), 256>>>(
        d_vnr, vW2, vb2, d_vn2, NB * NV, HD, HD, 1, 0, nullptr, nullptr, 0);

    // fused tail
    tail_kernel<<<NB, HD>>>(d_vn2, mW1, mb1, mW2, mb2, out);
}

// round 14
// speedup vs baseline: 1.2504x; 1.2504x over previous
#include <cuda_runtime.h>
#include <cuda_bf16.h>
#include <cstdint>

// ---------------- Problem constants ----------------
#define NB      64
#define NNODES  512
#define NV      64
#define HD      256
#define IN_DIM  128
#define OUT_DIM 10
#define TOTAL_N (NB * NNODES)        // 32768
#define EDGES   (NB * 16384)         // 1048576
#define CSR_CAP 128

// ---------------- Scratch ----------------
__device__ int   g_cnt[TOTAL_N];
__device__ float g_dinv[TOTAL_N];
__device__ int   g_csr[(long)TOTAL_N * CSR_CAP];
__device__ float g_wc[IN_DIM * HD];
__device__ float g_bc[HD];
__device__ float g_y[(long)TOTAL_N * IN_DIM];
__device__ float g_sc[TOTAL_N];
__device__ float g_g[(long)TOTAL_N * HD];
__device__ float g_t1[(long)TOTAL_N * HD];
__device__ float g_t[(long)TOTAL_N * HD];
__device__ float g_proto[NB * HD];
__device__ float g_pn[NB];
__device__ float g_ct[(long)NB * NV * NNODES];
__device__ float g_vn[(long)NB * NV * HD];
__device__ float g_vnr[(long)NB * NV * HD];
__device__ float g_vn2[(long)NB * NV * HD];

// ---------------- helpers ----------------
__device__ __forceinline__ float warp_sum(float v) {
    #pragma unroll
    for (int o = 16; o > 0; o >>= 1) v += __shfl_xor_sync(0xffffffff, v, o);
    return v;
}

__device__ __forceinline__ uint32_t smem_u32(const void* p) {
    uint32_t a;
    asm("{ .reg .u64 t; cvta.to.shared.u64 t, %1; cvt.u32.u64 %0, t; }" : "=r"(a) : "l"(p));
    return a;
}

__device__ __forceinline__ void cp_async16(uint32_t saddr, const void* gptr) {
    asm volatile("cp.async.cg.shared.global [%0], [%1], 16;" :: "r"(saddr), "l"(gptr));
}

__global__ void cnt_zero_kernel(int* __restrict__ cnt) {
    int i = blockIdx.x * blockDim.x + threadIdx.x;
    if (i < TOTAL_N) cnt[i] = 0;
}

__global__ void csr_fill_kernel(const int* __restrict__ src, const int* __restrict__ dst,
                                int* __restrict__ cnt, int* __restrict__ csr) {
    int e = blockIdx.x * blockDim.x + threadIdx.x;
    if (e >= EDGES) return;
    int s = src[e], d = dst[e];
    int pos = atomicAdd(&cnt[d], 1);
    if (pos < CSR_CAP) csr[(long)d * CSR_CAP + pos] = s;
}

__global__ void dinv_kernel(const int* __restrict__ cnt, float* __restrict__ dinv) {
    int i = blockIdx.x * blockDim.x + threadIdx.x;
    if (i < TOTAL_N) dinv[i] = rsqrtf(1.0f + (float)cnt[i]);
}

// ---------------- weight fold: block-internal split-K ----------------
__global__ __launch_bounds__(1024) void fold4_kernel(
    const float* __restrict__ W_emb, const float* __restrict__ b_emb,
    const float* __restrict__ W_gcn,
    float* __restrict__ wc, float* __restrict__ bc)
{
    __shared__ float sa[HD];
    __shared__ float pacc[4][HD];
    const int tid = threadIdx.x;
    const int ks = tid >> 8;
    const int c  = tid & 255;
    const int r  = blockIdx.x;

    if (tid < HD) sa[tid] = (r < IN_DIM) ? W_emb[(long)r * HD + tid] : b_emb[tid];
    __syncthreads();

    const int k0 = ks * 64;
    float acc = 0.f;
    #pragma unroll 8
    for (int k = 0; k < 64; k++)
        acc += sa[k0 + k] * W_gcn[(long)(k0 + k) * HD + c];
    pacc[ks][c] = acc;
    __syncthreads();

    if (ks == 0) {
        float tot = pacc[0][c] + pacc[1][c] + pacc[2][c] + pacc[3][c];
        if (r < IN_DIM) wc[(long)r * HD + c] = tot;
        else            bc[c] = tot;
    }
}

// ---------------- gather in x-space (R12 version — warp per node) ----------------
__global__ __launch_bounds__(256) void gcn_gather_x(
    const int* __restrict__ cnt, const int* __restrict__ csr,
    const float* __restrict__ dinv, const float4* __restrict__ x4,
    float4* __restrict__ y4, float* __restrict__ sc)
{
    int node = blockIdx.x * 8 + (threadIdx.x >> 5);
    int lane = threadIdx.x & 31;
    int mr = cnt[node];
    int m = mr > CSR_CAP ? CSR_CAP : mr;
    long base = (long)node * CSR_CAP;

    float inv = 1.0f / (1.0f + (float)mr);
    float rsd = dinv[node];

    float4 a = x4[(long)node * 32 + lane];
    float4 acc = make_float4(a.x * inv, a.y * inv, a.z * inv, a.w * inv);
    float cs = inv;

    int e = 0;
    for (; e + 4 <= m; e += 4) {
        int s0 = csr[base + e + 0], s1 = csr[base + e + 1];
        int s2 = csr[base + e + 2], s3 = csr[base + e + 3];
        float c0 = dinv[s0] * rsd, c1 = dinv[s1] * rsd;
        float c2 = dinv[s2] * rsd, c3 = dinv[s3] * rsd;
        float4 v0 = x4[(long)s0 * 32 + lane];
        float4 v1 = x4[(long)s1 * 32 + lane];
        float4 v2 = x4[(long)s2 * 32 + lane];
        float4 v3 = x4[(long)s3 * 32 + lane];
        acc.x += c0 * v0.x + c1 * v1.x + c2 * v2.x + c3 * v3.x;
        acc.y += c0 * v0.y + c1 * v1.y + c2 * v2.y + c3 * v3.y;
        acc.z += c0 * v0.z + c1 * v1.z + c2 * v2.z + c3 * v3.z;
        acc.w += c0 * v0.w + c1 * v1.w + c2 * v2.w + c3 * v3.w;
        cs += c0 + c1 + c2 + c3;
    }
    for (; e < m; e++) {
        int s0 = csr[base + e];
        float cc = dinv[s0] * rsd;
        float4 v = x4[(long)s0 * 32 + lane];
        acc.x += cc * v.x; acc.y += cc * v.y; acc.z += cc * v.z; acc.w += cc * v.w;
        cs += cc;
    }
    y4[(long)node * 32 + lane] = acc;
    if (lane == 0) sc[node] = cs;
}

// ---------------- 3xTF32 tensor-core GEMM, cp.async double-buffered ----------------
__device__ __forceinline__ void mma_tf32(float* d, const uint32_t* a, const uint32_t* b) {
    asm volatile(
        "mma.sync.aligned.m16n8k8.row.col.f32.tf32.tf32.f32 "
        "{%0,%1,%2,%3}, {%4,%5,%6,%7}, {%8,%9}, {%0,%1,%2,%3};\n"
        : "+f"(d[0]), "+f"(d[1]), "+f"(d[2]), "+f"(d[3])
        : "r"(a[0]), "r"(a[1]), "r"(a[2]), "r"(a[3]), "r"(b[0]), "r"(b[1]));
}

__device__ __forceinline__ void split_tf32(float v, uint32_t& hi, uint32_t& lo) {
    uint32_t h;
    asm("cvt.rna.tf32.f32 %0, %1;" : "=r"(h) : "f"(v));
    float l = v - __uint_as_float(h);
    uint32_t lw;
    asm("cvt.rna.tf32.f32 %0, %1;" : "=r"(lw) : "f"(l));
    hi = h; lo = lw;
}

#define TBM 128
#define TBN 128
#define TBK 32
#define ASTRIDE (TBK + 4)                 // 36
#define BSTRIDE (TBN + 4)                 // 132
#define ASZ (TBM * ASTRIDE)               // 4608 floats
#define BSZ (TBK * BSTRIDE)               // 4224 floats
#define GEMM_DB_SMEM ((2 * ASZ + 2 * BSZ) * 4)   // 70656 B

__global__ __launch_bounds__(256) void tf32x3_gemm_db(
    const float* __restrict__ A, const float* __restrict__ B,
    const float* __restrict__ bias, float* __restrict__ C,
    int M, int N, int K, int hasBias, int relu,
    const float* __restrict__ rowScale, const float* __restrict__ bias2, int hasRS)
{
    extern __shared__ float smp[];
    // layout: As[2] then Bs[2]
    const uint32_t sbase = smem_u32(smp);

    const int tid  = threadIdx.x;
    const int wid  = tid >> 5, lane = tid & 31;
    const int warpM = wid & 1;
    const int warpN = wid >> 1;
    const int grp = lane >> 2, tig = lane & 3;

    const int blockRow = blockIdx.y * TBM;
    const int blockCol = blockIdx.x * TBN;

    const int aRow  = tid >> 3;           // 0..31 (+32*rr)
    const int aCol  = (tid & 7) * 4;      // 0..28
    const int bRow8 = tid >> 5;           // 0..7 (+8*rr)
    const int bCol4 = (tid & 31) * 4;     // 0..124

    // per-stage smem byte offsets for this thread's cp.async targets
    auto a_soff = [&](int st, int r) { return (uint32_t)((st * ASZ + r * ASTRIDE + aCol) * 4); };
    auto b_soff = [&](int st, int rb) { return (uint32_t)((2 * ASZ + st * BSZ + rb * BSTRIDE + bCol4) * 4); };

    float acc[4][4][4];
    #pragma unroll
    for (int i = 0; i < 4; i++)
        #pragma unroll
        for (int j = 0; j < 4; j++)
            #pragma unroll
            for (int r = 0; r < 4; r++) acc[i][j][r] = 0.f;

    // prologue: stage 0 loads for bk=0
    {
        #pragma unroll
        for (int rr = 0; rr < 4; rr++) {
            int r = aRow + 32 * rr;
            cp_async16(sbase + a_soff(0, r), A + (long)(blockRow + r) * K + aCol);
            int rb = bRow8 + 8 * rr;
            cp_async16(sbase + b_soff(0, rb), B + (long)rb * N + blockCol + bCol4);
        }
        asm volatile("cp.async.commit_group;" ::: "memory");
    }

    int cur = 0;
    for (int bk = 0; bk < K; bk += TBK) {
        const int hasNext = (bk + TBK < K);
        if (hasNext) {
            int nxt = cur ^ 1;
            #pragma unroll
            for (int rr = 0; rr < 4; rr++) {
                int r = aRow + 32 * rr;
                cp_async16(sbase + a_soff(nxt, r),
                           A + (long)(blockRow + r) * K + (bk + TBK) + aCol);
                int rb = bRow8 + 8 * rr;
                cp_async16(sbase + b_soff(nxt, rb),
                           B + (long)(bk + TBK + rb) * N + blockCol + bCol4);
            }
            asm volatile("cp.async.commit_group;" ::: "memory");
            asm volatile("cp.async.wait_group 1;" ::: "memory");
        } else {
            asm volatile("cp.async.wait_group 0;" ::: "memory");
        }
        __syncthreads();

        const float* Asb = smp + cur * ASZ;
        const float* Bsb = smp + 2 * ASZ + cur * BSZ;

        #pragma unroll
        for (int kk = 0; kk < TBK; kk += 8) {
            uint32_t ah[4][4], al[4][4];
            #pragma unroll
            for (int mi = 0; mi < 4; mi++) {
                int r0 = warpM * 64 + mi * 16 + grp;
                split_tf32(Asb[(r0    ) * ASTRIDE + kk + tig    ], ah[mi][0], al[mi][0]);
                split_tf32(Asb[(r0 + 8) * ASTRIDE + kk + tig    ], ah[mi][1], al[mi][1]);
                split_tf32(Asb[(r0    ) * ASTRIDE + kk + tig + 4], ah[mi][2], al[mi][2]);
                split_tf32(Asb[(r0 + 8) * ASTRIDE + kk + tig + 4], ah[mi][3], al[mi][3]);
            }
            uint32_t bh[4][2], bl[4][2];
            #pragma unroll
            for (int ni = 0; ni < 4; ni++) {
                int c0 = warpN * 32 + ni * 8 + grp;
                split_tf32(Bsb[(kk + tig    ) * BSTRIDE + c0], bh[ni][0], bl[ni][0]);
                split_tf32(Bsb[(kk + tig + 4) * BSTRIDE + c0], bh[ni][1], bl[ni][1]);
            }
            #pragma unroll
            for (int mi = 0; mi < 4; mi++)
                #pragma unroll
                for (int ni = 0; ni < 4; ni++) {
                    mma_tf32(acc[mi][ni], al[mi], bh[ni]);
                    mma_tf32(acc[mi][ni], ah[mi], bl[ni]);
                    mma_tf32(acc[mi][ni], ah[mi], bh[ni]);
                }
        }
        __syncthreads();
        cur ^= 1;
    }

    #pragma unroll
    for (int mi = 0; mi < 4; mi++) {
        int row = blockRow + warpM * 64 + mi * 16 + grp;
        float rs0 = 0.f, rs1 = 0.f;
        if (hasRS) { rs0 = rowScale[row]; rs1 = rowScale[row + 8]; }
        #pragma unroll
        for (int ni = 0; ni < 4; ni++) {
            int col = blockCol + warpN * 32 + ni * 8 + 2 * tig;
            float2 bv = make_float2(0.f, 0.f);
            if (hasBias) bv = *reinterpret_cast<const float2*>(&bias[col]);
            float2 b2 = make_float2(0.f, 0.f);
            if (hasRS) b2 = *reinterpret_cast<const float2*>(&bias2[col]);
            float2 o0 = make_float2(acc[mi][ni][0] + bv.x + rs0 * b2.x,
                                    acc[mi][ni][1] + bv.y + rs0 * b2.y);
            float2 o1 = make_float2(acc[mi][ni][2] + bv.x + rs1 * b2.x,
                                    acc[mi][ni][3] + bv.y + rs1 * b2.y);
            if (relu) {
                o0.x = fmaxf(o0.x, 0.f); o0.y = fmaxf(o0.y, 0.f);
                o1.x = fmaxf(o1.x, 0.f); o1.y = fmaxf(o1.y, 0.f);
            }
            *reinterpret_cast<float2*>(&C[(long)row * N + col])       = o0;
            *reinterpret_cast<float2*>(&C[(long)(row + 8) * N + col]) = o1;
        }
    }
}

// ---------------- batched 3xTF32 GEMM for vn (unchanged from R12) ----------------
__global__ __launch_bounds__(256) void vn_gemm(
    const float* __restrict__ Am, const float* __restrict__ Bm, float* __restrict__ Cm)
{
    __shared__ float As[NV * ASTRIDE];
    __shared__ float Bs[TBK * BSTRIDE];

    const int tid  = threadIdx.x;
    const int wid  = tid >> 5, lane = tid & 31;
    const int warpM = wid & 1;
    const int warpN = wid >> 1;
    const int grp = lane >> 2, tig = lane & 3;

    const int z = blockIdx.z;
    const float* A = Am + (long)z * NV * NNODES;
    const float* B = Bm + (long)z * NNODES * HD;
    float*       C = Cm + (long)z * NV * HD;
    const int blockCol = blockIdx.x * TBN;

    const int aRow  = tid >> 3;
    const int aCol  = (tid & 7) * 4;
    const int bRow8 = tid >> 5;
    const int bCol4 = (tid & 31) * 4;

    float acc[2][4][4];
    #pragma unroll
    for (int i = 0; i < 2; i++)
        #pragma unroll
        for (int j = 0; j < 4; j++)
            #pragma unroll
            for (int r = 0; r < 4; r++) acc[i][j][r] = 0.f;

    for (int bk = 0; bk < NNODES; bk += TBK) {
        #pragma unroll
        for (int rr = 0; rr < 2; rr++) {
            int r = aRow + 32 * rr;
            float4 a4 = *reinterpret_cast<const float4*>(A + (long)r * NNODES + bk + aCol);
            *reinterpret_cast<float4*>(&As[r * ASTRIDE + aCol]) = a4;
        }
        #pragma unroll
        for (int rr = 0; rr < 4; rr++) {
            int rb = bRow8 + 8 * rr;
            float4 b4 = *reinterpret_cast<const float4*>(B + (long)(bk + rb) * HD + blockCol + bCol4);
            *reinterpret_cast<float4*>(&Bs[rb * BSTRIDE + bCol4]) = b4;
        }
        __syncthreads();

        #pragma unroll
        for (int kk = 0; kk < TBK; kk += 8) {
            uint32_t ah[2][4], al[2][4];
            #pragma unroll
            for (int mi = 0; mi < 2; mi++) {
                int r0 = warpM * 32 + mi * 16 + grp;
                split_tf32(As[(r0    ) * ASTRIDE + kk + tig    ], ah[mi][0], al[mi][0]);
                split_tf32(As[(r0 + 8) * ASTRIDE + kk + tig    ], ah[mi][1], al[mi][1]);
                split_tf32(As[(r0    ) * ASTRIDE + kk + tig + 4], ah[mi][2], al[mi][2]);
                split_tf32(As[(r0 + 8) * ASTRIDE + kk + tig + 4], ah[mi][3], al[mi][3]);
            }
            uint32_t bh[4][2], bl[4][2];
            #pragma unroll
            for (int ni = 0; ni < 4; ni++) {
                int c0 = warpN * 32 + ni * 8 + grp;
                split_tf32(Bs[(kk + tig    ) * BSTRIDE + c0], bh[ni][0], bl[ni][0]);
                split_tf32(Bs[(kk + tig + 4) * BSTRIDE + c0], bh[ni][1], bl[ni][1]);
            }
            #pragma unroll
            for (int mi = 0; mi < 2; mi++)
                #pragma unroll
                for (int ni = 0; ni < 4; ni++) {
                    mma_tf32(acc[mi][ni], al[mi], bh[ni]);
                    mma_tf32(acc[mi][ni], ah[mi], bl[ni]);
                    mma_tf32(acc[mi][ni], ah[mi], bh[ni]);
                }
        }
        __syncthreads();
    }

    #pragma unroll
    for (int mi = 0; mi < 2; mi++) {
        int row = warpM * 32 + mi * 16 + grp;
        #pragma unroll
        for (int ni = 0; ni < 4; ni++) {
            int col = blockCol + warpN * 32 + ni * 8 + 2 * tig;
            *reinterpret_cast<float2*>(&C[(long)row * HD + col]) =
                make_float2(acc[mi][ni][0], acc[mi][ni][1]);
            *reinterpret_cast<float2*>(&C[(long)(row + 8) * HD + col]) =
                make_float2(acc[mi][ni][2], acc[mi][ni][3]);
        }
    }
}

// ---------------- proto mean + norm (fused) ----------------
__global__ void proto_pn_kernel(const float* __restrict__ t, float* __restrict__ proto,
                                float* __restrict__ pn) {
    int b = blockIdx.x, h = threadIdx.x;
    const float* tb = t + (long)b * NNODES * HD + h;
    float s = 0.f;
    #pragma unroll 4
    for (int n = 0; n < NNODES; n++) s += tb[(long)n * HD];
    float p = s * (1.0f / NNODES);
    proto[b * HD + h] = p;
    __shared__ float red[8];
    float sq = warp_sum(p * p);
    if ((h & 31) == 0) red[h >> 5] = sq;
    __syncthreads();
    if (h == 0) {
        float tot = 0.f;
        #pragma unroll
        for (int i = 0; i < 8; i++) tot += red[i];
        pn[b] = fmaxf(sqrtf(tot), 1e-8f);
    }
}

// ---------------- fused attention + row-normalized mw (writes TRANSPOSED c) ----------------
__global__ void att_mw_kernel(const float* __restrict__ t, const float* __restrict__ proto,
                              const float* __restrict__ pn, const float* __restrict__ ew,
                              float* __restrict__ ct) {
    int warp = (blockIdx.x * blockDim.x + threadIdx.x) >> 5;
    int lane = threadIdx.x & 31;
    if (warp >= TOTAL_N) return;
    int b  = warp >> 9;
    int nl = warp & 511;
    const float* tr = t + (long)warp * HD;
    const float* pr = proto + b * HD;
    float s2 = 0.f, dp = 0.f;
    #pragma unroll
    for (int h = lane; h < HD; h += 32) {
        float tv = tr[h];
        s2 += tv * tv;
        dp += tv * pr[h];
    }
    s2 = warp_sum(s2);
    dp = warp_sum(dp);
    float tn = fmaxf(sqrtf(s2), 1e-8f);
    float a  = 0.5f * (1.0f + dp / (tn * pn[b]));

    const float* er = ew + (long)warp * NV;
    float m0 = er[lane]      * a;
    float m1 = er[lane + 32] * a;
    float rs = warp_sum(m0 + m1);
    float d  = (rs == 0.f) ? 1.f : rs;
    ct[((long)b * NV + lane)      * NNODES + nl] = m0 / d;
    ct[((long)b * NV + lane + 32) * NNODES + nl] = m1 / d;
}

// ---------------- fused tail: gf mean + MLP1 + out ----------------
__global__ void tail_kernel(const float* __restrict__ vn2,
                            const float* __restrict__ mW1, const float* __restrict__ mb1,
                            const float* __restrict__ mW2, const float* __restrict__ mb2,
                            float* __restrict__ out) {
    int b = blockIdx.x, h = threadIdx.x;
    __shared__ float sgf[HD];
    __shared__ float sm1[HD];

    float s = 0.f;
    #pragma unroll 4
    for (int v = 0; v < NV; v++) s += vn2[((long)b * NV + v) * HD + h];
    sgf[h] = s * (1.0f / NV);
    __syncthreads();

    float acc = 0.f;
    #pragma unroll 4
    for (int k = 0; k < HD; k++) acc += sgf[k] * mW1[(long)k * HD + h];
    sm1[h] = fmaxf(acc + mb1[h], 0.f);
    __syncthreads();

    if (h < OUT_DIM) {
        float a2 = 0.f;
        #pragma unroll 4
        for (int k = 0; k < HD; k++) a2 += sm1[k] * mW2[(long)k * OUT_DIM + h];
        out[b * OUT_DIM + h] = a2 + mb2[h];
    }
}

// ---------------- launch ----------------
extern "C" void kernel_launch(void* const* d_in, const int* in_sizes, int n_in,
                              void* d_out, int out_size) {
    const float* x     = (const float*)d_in[0];
    const int*   esrc  = (const int*)  d_in[1];
    const int*   edst  = (const int*)  d_in[2];
    const float* W_emb = (const float*)d_in[3];
    const float* b_emb = (const float*)d_in[4];
    const float* W_gcn = (const float*)d_in[5];
    const float* b_gcn = (const float*)d_in[6];
    const float* aW1   = (const float*)d_in[7];
    const float* ab1   = (const float*)d_in[8];
    const float* aW2   = (const float*)d_in[9];
    const float* ab2   = (const float*)d_in[10];
    const float* vW1   = (const float*)d_in[11];
    const float* vb1   = (const float*)d_in[12];
    const float* vW2   = (const float*)d_in[13];
    const float* vb2   = (const float*)d_in[14];
    const float* mW1   = (const float*)d_in[15];
    const float* mb1   = (const float*)d_in[16];
    const float* mW2   = (const float*)d_in[17];
    const float* mb2   = (const float*)d_in[18];
    const float* ew    = (const float*)d_in[19];
    float* out = (float*)d_out;

    float *d_dinv, *d_wc, *d_bc, *d_y, *d_sc, *d_g, *d_t1, *d_t, *d_proto, *d_pn,
          *d_ct, *d_vn, *d_vnr, *d_vn2;
    int *d_cnt, *d_csr;
    cudaGetSymbolAddress((void**)&d_cnt,   g_cnt);
    cudaGetSymbolAddress((void**)&d_dinv,  g_dinv);
    cudaGetSymbolAddress((void**)&d_csr,   g_csr);
    cudaGetSymbolAddress((void**)&d_wc,    g_wc);
    cudaGetSymbolAddress((void**)&d_bc,    g_bc);
    cudaGetSymbolAddress((void**)&d_y,     g_y);
    cudaGetSymbolAddress((void**)&d_sc,    g_sc);
    cudaGetSymbolAddress((void**)&d_g,     g_g);
    cudaGetSymbolAddress((void**)&d_t1,    g_t1);
    cudaGetSymbolAddress((void**)&d_t,     g_t);
    cudaGetSymbolAddress((void**)&d_proto, g_proto);
    cudaGetSymbolAddress((void**)&d_pn,    g_pn);
    cudaGetSymbolAddress((void**)&d_ct,    g_ct);
    cudaGetSymbolAddress((void**)&d_vn,    g_vn);
    cudaGetSymbolAddress((void**)&d_vnr,   g_vnr);
    cudaGetSymbolAddress((void**)&d_vn2,   g_vn2);

    static int smem_set = 0;
    if (!smem_set) {
        cudaFuncSetAttribute(tf32x3_gemm_db,
                             cudaFuncAttributeMaxDynamicSharedMemorySize, GEMM_DB_SMEM);
        smem_set = 1;
    }

    // CSR build (counts double as degrees)
    cnt_zero_kernel<<<TOTAL_N / 256, 256>>>(d_cnt);
    csr_fill_kernel<<<EDGES / 256, 256>>>(esrc, edst, d_cnt, d_csr);
    dinv_kernel<<<TOTAL_N / 256, 256>>>(d_cnt, d_dinv);

    // weight fold (block-internal split-K)
    fold4_kernel<<<IN_DIM + 1, 1024>>>(W_emb, b_emb, W_gcn, d_wc, d_bc);

    // sparse aggregation in x-space
    gcn_gather_x<<<TOTAL_N / 8, 256>>>(d_cnt, d_csr, d_dinv,
                                       (const float4*)x, (float4*)d_y, d_sc);

    // g = relu(y @ Wc + sc*bc + b_gcn)
    tf32x3_gemm_db<<<dim3(HD / TBN, TOTAL_N / TBM), 256, GEMM_DB_SMEM>>>(
        d_y, d_wc, b_gcn, d_g, TOTAL_N, HD, IN_DIM, 1, 1, d_sc, d_bc, 1);

    // affinity MLP
    tf32x3_gemm_db<<<dim3(HD / TBN, TOTAL_N / TBM), 256, GEMM_DB_SMEM>>>(
        d_g, aW1, ab1, d_t1, TOTAL_N, HD, HD, 1, 1, nullptr, nullptr, 0);
    tf32x3_gemm_db<<<dim3(HD / TBN, TOTAL_N / TBM), 256, GEMM_DB_SMEM>>>(
        d_t1, aW2, ab2, d_t, TOTAL_N, HD, HD, 1, 0, nullptr, nullptr, 0);

    proto_pn_kernel<<<NB, HD>>>(d_t, d_proto, d_pn);
    att_mw_kernel<<<TOTAL_N / 8, 256>>>(d_t, d_proto, d_pn, ew, d_ct);

    // vn[b] = ct[b] @ g[b]
    vn_gemm<<<dim3(HD / TBN, 1, NB), 256>>>(d_ct, d_g, d_vn);

    // virtual-node MLP
    tf32x3_gemm_db<<<dim3(HD / TBN, (NB * NV) / TBM), 256, GEMM_DB_SMEM>>>(
        d_vn, vW1, vb1, d_vnr, NB * NV, HD, HD, 1, 1, nullptr, nullptr, 0);
    tf32x3_gemm_db<<<dim3(HD / TBN, (NB * NV) / TBM), 256, GEMM_DB_SMEM>>>(
        d_vnr, vW2, vb2, d_vn2, NB * NV, HD, HD, 1, 0, nullptr, nullptr, 0);

    // fused tail
    tail_kernel<<<NB, HD>>>(d_vn2, mW1, mb1, mW2, mb2, out);
}

// round 15
// speedup vs baseline: 1.2997x; 1.0395x over previous
#include <cuda_runtime.h>
#include <cuda_bf16.h>
#include <cstdint>

// ---------------- Problem constants ----------------
#define NB      64
#define NNODES  512
#define NV      64
#define HD      256
#define IN_DIM  128
#define OUT_DIM 10
#define TOTAL_N (NB * NNODES)        // 32768
#define EDGES   (NB * 16384)         // 1048576
#define CSR_CAP 128

// ---------------- Scratch ----------------
__device__ int   g_cnt[TOTAL_N];
__device__ float g_dinv[TOTAL_N];
__device__ int   g_csr[(long)TOTAL_N * CSR_CAP];
__device__ float g_wc[IN_DIM * HD];
__device__ float g_bc[HD];
__device__ float g_y[(long)TOTAL_N * IN_DIM];
__device__ float g_sc[TOTAL_N];
__device__ float g_g[(long)TOTAL_N * HD];
__device__ float g_t1[(long)TOTAL_N * HD];
__device__ float g_t[(long)TOTAL_N * HD];
__device__ float g_proto[NB * HD];
__device__ float g_pn[NB];
__device__ float g_ct[(long)NB * NV * NNODES];
__device__ float g_vn[(long)NB * NV * HD];
__device__ float g_vnr[(long)NB * NV * HD];
__device__ float g_vn2[(long)NB * NV * HD];

// ---------------- helpers ----------------
__device__ __forceinline__ float warp_sum(float v) {
    #pragma unroll
    for (int o = 16; o > 0; o >>= 1) v += __shfl_xor_sync(0xffffffff, v, o);
    return v;
}

__device__ __forceinline__ uint32_t smem_u32(const void* p) {
    uint32_t a;
    asm("{ .reg .u64 t; cvta.to.shared.u64 t, %1; cvt.u32.u64 %0, t; }" : "=r"(a) : "l"(p));
    return a;
}

__device__ __forceinline__ void cp_async16(uint32_t saddr, const void* gptr) {
    asm volatile("cp.async.cg.shared.global [%0], [%1], 16;" :: "r"(saddr), "l"(gptr));
}

__global__ void cnt_zero_kernel(int* __restrict__ cnt) {
    int i = blockIdx.x * blockDim.x + threadIdx.x;
    if (i < TOTAL_N) cnt[i] = 0;
}

__global__ void csr_fill_kernel(const int* __restrict__ src, const int* __restrict__ dst,
                                int* __restrict__ cnt, int* __restrict__ csr) {
    int e = blockIdx.x * blockDim.x + threadIdx.x;
    if (e >= EDGES) return;
    int s = src[e], d = dst[e];
    int pos = atomicAdd(&cnt[d], 1);
    if (pos < CSR_CAP) csr[(long)d * CSR_CAP + pos] = s;
}

__global__ void dinv_kernel(const int* __restrict__ cnt, float* __restrict__ dinv) {
    int i = blockIdx.x * blockDim.x + threadIdx.x;
    if (i < TOTAL_N) dinv[i] = rsqrtf(1.0f + (float)cnt[i]);
}

// ---------------- weight fold: block-internal split-K ----------------
__global__ __launch_bounds__(1024) void fold4_kernel(
    const float* __restrict__ W_emb, const float* __restrict__ b_emb,
    const float* __restrict__ W_gcn,
    float* __restrict__ wc, float* __restrict__ bc)
{
    __shared__ float sa[HD];
    __shared__ float pacc[4][HD];
    const int tid = threadIdx.x;
    const int ks = tid >> 8;
    const int c  = tid & 255;
    const int r  = blockIdx.x;

    if (tid < HD) sa[tid] = (r < IN_DIM) ? W_emb[(long)r * HD + tid] : b_emb[tid];
    __syncthreads();

    const int k0 = ks * 64;
    float acc = 0.f;
    #pragma unroll 8
    for (int k = 0; k < 64; k++)
        acc += sa[k0 + k] * W_gcn[(long)(k0 + k) * HD + c];
    pacc[ks][c] = acc;
    __syncthreads();

    if (ks == 0) {
        float tot = pacc[0][c] + pacc[1][c] + pacc[2][c] + pacc[3][c];
        if (r < IN_DIM) wc[(long)r * HD + c] = tot;
        else            bc[c] = tot;
    }
}

// ---------------- gather in x-space (warp per node, 8-wide edge unroll) ----------------
__global__ __launch_bounds__(256) void gcn_gather_x(
    const int* __restrict__ cnt, const int* __restrict__ csr,
    const float* __restrict__ dinv, const float4* __restrict__ x4,
    float4* __restrict__ y4, float* __restrict__ sc)
{
    int node = blockIdx.x * 8 + (threadIdx.x >> 5);
    int lane = threadIdx.x & 31;
    int mr = cnt[node];
    int m = mr > CSR_CAP ? CSR_CAP : mr;
    long base = (long)node * CSR_CAP;

    float inv = 1.0f / (1.0f + (float)mr);
    float rsd = dinv[node];

    float4 a = x4[(long)node * 32 + lane];
    float4 acc = make_float4(a.x * inv, a.y * inv, a.z * inv, a.w * inv);
    float cs = inv;

    int e = 0;
    for (; e + 8 <= m; e += 8) {
        int s0 = csr[base + e + 0], s1 = csr[base + e + 1];
        int s2 = csr[base + e + 2], s3 = csr[base + e + 3];
        int s4 = csr[base + e + 4], s5 = csr[base + e + 5];
        int s6 = csr[base + e + 6], s7 = csr[base + e + 7];
        float c0 = dinv[s0] * rsd, c1 = dinv[s1] * rsd;
        float c2 = dinv[s2] * rsd, c3 = dinv[s3] * rsd;
        float c4 = dinv[s4] * rsd, c5 = dinv[s5] * rsd;
        float c6 = dinv[s6] * rsd, c7 = dinv[s7] * rsd;
        float4 v0 = x4[(long)s0 * 32 + lane];
        float4 v1 = x4[(long)s1 * 32 + lane];
        float4 v2 = x4[(long)s2 * 32 + lane];
        float4 v3 = x4[(long)s3 * 32 + lane];
        float4 v4 = x4[(long)s4 * 32 + lane];
        float4 v5 = x4[(long)s5 * 32 + lane];
        float4 v6 = x4[(long)s6 * 32 + lane];
        float4 v7 = x4[(long)s7 * 32 + lane];
        acc.x += c0 * v0.x + c1 * v1.x + c2 * v2.x + c3 * v3.x
               + c4 * v4.x + c5 * v5.x + c6 * v6.x + c7 * v7.x;
        acc.y += c0 * v0.y + c1 * v1.y + c2 * v2.y + c3 * v3.y
               + c4 * v4.y + c5 * v5.y + c6 * v6.y + c7 * v7.y;
        acc.z += c0 * v0.z + c1 * v1.z + c2 * v2.z + c3 * v3.z
               + c4 * v4.z + c5 * v5.z + c6 * v6.z + c7 * v7.z;
        acc.w += c0 * v0.w + c1 * v1.w + c2 * v2.w + c3 * v3.w
               + c4 * v4.w + c5 * v5.w + c6 * v6.w + c7 * v7.w;
        cs += c0 + c1 + c2 + c3 + c4 + c5 + c6 + c7;
    }
    for (; e + 4 <= m; e += 4) {
        int s0 = csr[base + e + 0], s1 = csr[base + e + 1];
        int s2 = csr[base + e + 2], s3 = csr[base + e + 3];
        float c0 = dinv[s0] * rsd, c1 = dinv[s1] * rsd;
        float c2 = dinv[s2] * rsd, c3 = dinv[s3] * rsd;
        float4 v0 = x4[(long)s0 * 32 + lane];
        float4 v1 = x4[(long)s1 * 32 + lane];
        float4 v2 = x4[(long)s2 * 32 + lane];
        float4 v3 = x4[(long)s3 * 32 + lane];
        acc.x += c0 * v0.x + c1 * v1.x + c2 * v2.x + c3 * v3.x;
        acc.y += c0 * v0.y + c1 * v1.y + c2 * v2.y + c3 * v3.y;
        acc.z += c0 * v0.z + c1 * v1.z + c2 * v2.z + c3 * v3.z;
        acc.w += c0 * v0.w + c1 * v1.w + c2 * v2.w + c3 * v3.w;
        cs += c0 + c1 + c2 + c3;
    }
    for (; e < m; e++) {
        int s0 = csr[base + e];
        float cc = dinv[s0] * rsd;
        float4 v = x4[(long)s0 * 32 + lane];
        acc.x += cc * v.x; acc.y += cc * v.y; acc.z += cc * v.z; acc.w += cc * v.w;
        cs += cc;
    }
    y4[(long)node * 32 + lane] = acc;
    if (lane == 0) sc[node] = cs;
}

// ---------------- 3xTF32 tensor-core GEMM, cp.async double-buffered ----------------
__device__ __forceinline__ void mma_tf32(float* d, const uint32_t* a, const uint32_t* b) {
    asm volatile(
        "mma.sync.aligned.m16n8k8.row.col.f32.tf32.tf32.f32 "
        "{%0,%1,%2,%3}, {%4,%5,%6,%7}, {%8,%9}, {%0,%1,%2,%3};\n"
        : "+f"(d[0]), "+f"(d[1]), "+f"(d[2]), "+f"(d[3])
        : "r"(a[0]), "r"(a[1]), "r"(a[2]), "r"(a[3]), "r"(b[0]), "r"(b[1]));
}

__device__ __forceinline__ void split_tf32(float v, uint32_t& hi, uint32_t& lo) {
    uint32_t h;
    asm("cvt.rna.tf32.f32 %0, %1;" : "=r"(h) : "f"(v));
    float l = v - __uint_as_float(h);
    uint32_t lw;
    asm("cvt.rna.tf32.f32 %0, %1;" : "=r"(lw) : "f"(l));
    hi = h; lo = lw;
}

#define TBM 128
#define TBN 128
#define TBK 32
#define ASTRIDE (TBK + 4)                 // 36
#define BSTRIDE (TBN + 4)                 // 132
#define ASZ (TBM * ASTRIDE)               // 4608 floats
#define BSZ (TBK * BSTRIDE)               // 4224 floats
#define GEMM_DB_SMEM ((2 * ASZ + 2 * BSZ) * 4)    // 70656 B
#define VASZ (NV * ASTRIDE)               // 2304 floats
#define VN_DB_SMEM ((2 * VASZ + 2 * BSZ) * 4)     // 52224 B

__global__ __launch_bounds__(256) void tf32x3_gemm_db(
    const float* __restrict__ A, const float* __restrict__ B,
    const float* __restrict__ bias, float* __restrict__ C,
    int M, int N, int K, int hasBias, int relu,
    const float* __restrict__ rowScale, const float* __restrict__ bias2, int hasRS)
{
    extern __shared__ float smp[];
    const uint32_t sbase = smem_u32(smp);

    const int tid  = threadIdx.x;
    const int wid  = tid >> 5, lane = tid & 31;
    const int warpM = wid & 1;
    const int warpN = wid >> 1;
    const int grp = lane >> 2, tig = lane & 3;

    const int blockRow = blockIdx.y * TBM;
    const int blockCol = blockIdx.x * TBN;

    const int aRow  = tid >> 3;
    const int aCol  = (tid & 7) * 4;
    const int bRow8 = tid >> 5;
    const int bCol4 = (tid & 31) * 4;

    auto a_soff = [&](int st, int r) { return (uint32_t)((st * ASZ + r * ASTRIDE + aCol) * 4); };
    auto b_soff = [&](int st, int rb) { return (uint32_t)((2 * ASZ + st * BSZ + rb * BSTRIDE + bCol4) * 4); };

    float acc[4][4][4];
    #pragma unroll
    for (int i = 0; i < 4; i++)
        #pragma unroll
        for (int j = 0; j < 4; j++)
            #pragma unroll
            for (int r = 0; r < 4; r++) acc[i][j][r] = 0.f;

    {
        #pragma unroll
        for (int rr = 0; rr < 4; rr++) {
            int r = aRow + 32 * rr;
            cp_async16(sbase + a_soff(0, r), A + (long)(blockRow + r) * K + aCol);
            int rb = bRow8 + 8 * rr;
            cp_async16(sbase + b_soff(0, rb), B + (long)rb * N + blockCol + bCol4);
        }
        asm volatile("cp.async.commit_group;" ::: "memory");
    }

    int cur = 0;
    for (int bk = 0; bk < K; bk += TBK) {
        const int hasNext = (bk + TBK < K);
        if (hasNext) {
            int nxt = cur ^ 1;
            #pragma unroll
            for (int rr = 0; rr < 4; rr++) {
                int r = aRow + 32 * rr;
                cp_async16(sbase + a_soff(nxt, r),
                           A + (long)(blockRow + r) * K + (bk + TBK) + aCol);
                int rb = bRow8 + 8 * rr;
                cp_async16(sbase + b_soff(nxt, rb),
                           B + (long)(bk + TBK + rb) * N + blockCol + bCol4);
            }
            asm volatile("cp.async.commit_group;" ::: "memory");
            asm volatile("cp.async.wait_group 1;" ::: "memory");
        } else {
            asm volatile("cp.async.wait_group 0;" ::: "memory");
        }
        __syncthreads();

        const float* Asb = smp + cur * ASZ;
        const float* Bsb = smp + 2 * ASZ + cur * BSZ;

        #pragma unroll
        for (int kk = 0; kk < TBK; kk += 8) {
            uint32_t ah[4][4], al[4][4];
            #pragma unroll
            for (int mi = 0; mi < 4; mi++) {
                int r0 = warpM * 64 + mi * 16 + grp;
                split_tf32(Asb[(r0    ) * ASTRIDE + kk + tig    ], ah[mi][0], al[mi][0]);
                split_tf32(Asb[(r0 + 8) * ASTRIDE + kk + tig    ], ah[mi][1], al[mi][1]);
                split_tf32(Asb[(r0    ) * ASTRIDE + kk + tig + 4], ah[mi][2], al[mi][2]);
                split_tf32(Asb[(r0 + 8) * ASTRIDE + kk + tig + 4], ah[mi][3], al[mi][3]);
            }
            uint32_t bh[4][2], bl[4][2];
            #pragma unroll
            for (int ni = 0; ni < 4; ni++) {
                int c0 = warpN * 32 + ni * 8 + grp;
                split_tf32(Bsb[(kk + tig    ) * BSTRIDE + c0], bh[ni][0], bl[ni][0]);
                split_tf32(Bsb[(kk + tig + 4) * BSTRIDE + c0], bh[ni][1], bl[ni][1]);
            }
            #pragma unroll
            for (int mi = 0; mi < 4; mi++)
                #pragma unroll
                for (int ni = 0; ni < 4; ni++) {
                    mma_tf32(acc[mi][ni], al[mi], bh[ni]);
                    mma_tf32(acc[mi][ni], ah[mi], bl[ni]);
                    mma_tf32(acc[mi][ni], ah[mi], bh[ni]);
                }
        }
        __syncthreads();
        cur ^= 1;
    }

    #pragma unroll
    for (int mi = 0; mi < 4; mi++) {
        int row = blockRow + warpM * 64 + mi * 16 + grp;
        float rs0 = 0.f, rs1 = 0.f;
        if (hasRS) { rs0 = rowScale[row]; rs1 = rowScale[row + 8]; }
        #pragma unroll
        for (int ni = 0; ni < 4; ni++) {
            int col = blockCol + warpN * 32 + ni * 8 + 2 * tig;
            float2 bv = make_float2(0.f, 0.f);
            if (hasBias) bv = *reinterpret_cast<const float2*>(&bias[col]);
            float2 b2 = make_float2(0.f, 0.f);
            if (hasRS) b2 = *reinterpret_cast<const float2*>(&bias2[col]);
            float2 o0 = make_float2(acc[mi][ni][0] + bv.x + rs0 * b2.x,
                                    acc[mi][ni][1] + bv.y + rs0 * b2.y);
            float2 o1 = make_float2(acc[mi][ni][2] + bv.x + rs1 * b2.x,
                                    acc[mi][ni][3] + bv.y + rs1 * b2.y);
            if (relu) {
                o0.x = fmaxf(o0.x, 0.f); o0.y = fmaxf(o0.y, 0.f);
                o1.x = fmaxf(o1.x, 0.f); o1.y = fmaxf(o1.y, 0.f);
            }
            *reinterpret_cast<float2*>(&C[(long)row * N + col])       = o0;
            *reinterpret_cast<float2*>(&C[(long)(row + 8) * N + col]) = o1;
        }
    }
}

// ---------------- batched 3xTF32 GEMM for vn, cp.async double-buffered ----------------
__global__ __launch_bounds__(256) void vn_gemm_db(
    const float* __restrict__ Am, const float* __restrict__ Bm, float* __restrict__ Cm)
{
    extern __shared__ float smp[];
    const uint32_t sbase = smem_u32(smp);

    const int tid  = threadIdx.x;
    const int wid  = tid >> 5, lane = tid & 31;
    const int warpM = wid & 1;
    const int warpN = wid >> 1;
    const int grp = lane >> 2, tig = lane & 3;

    const int z = blockIdx.z;
    const float* A = Am + (long)z * NV * NNODES;
    const float* B = Bm + (long)z * NNODES * HD;
    float*       C = Cm + (long)z * NV * HD;
    const int blockCol = blockIdx.x * TBN;

    const int aRow  = tid >> 3;           // 0..31 (+32)
    const int aCol  = (tid & 7) * 4;
    const int bRow8 = tid >> 5;
    const int bCol4 = (tid & 31) * 4;

    auto a_soff = [&](int st, int r) { return (uint32_t)((st * VASZ + r * ASTRIDE + aCol) * 4); };
    auto b_soff = [&](int st, int rb) { return (uint32_t)((2 * VASZ + st * BSZ + rb * BSTRIDE + bCol4) * 4); };

    float acc[2][4][4];
    #pragma unroll
    for (int i = 0; i < 2; i++)
        #pragma unroll
        for (int j = 0; j < 4; j++)
            #pragma unroll
            for (int r = 0; r < 4; r++) acc[i][j][r] = 0.f;

    {
        #pragma unroll
        for (int rr = 0; rr < 2; rr++) {
            int r = aRow + 32 * rr;
            cp_async16(sbase + a_soff(0, r), A + (long)r * NNODES + aCol);
        }
        #pragma unroll
        for (int rr = 0; rr < 4; rr++) {
            int rb = bRow8 + 8 * rr;
            cp_async16(sbase + b_soff(0, rb), B + (long)rb * HD + blockCol + bCol4);
        }
        asm volatile("cp.async.commit_group;" ::: "memory");
    }

    int cur = 0;
    for (int bk = 0; bk < NNODES; bk += TBK) {
        const int hasNext = (bk + TBK < NNODES);
        if (hasNext) {
            int nxt = cur ^ 1;
            #pragma unroll
            for (int rr = 0; rr < 2; rr++) {
                int r = aRow + 32 * rr;
                cp_async16(sbase + a_soff(nxt, r), A + (long)r * NNODES + (bk + TBK) + aCol);
            }
            #pragma unroll
            for (int rr = 0; rr < 4; rr++) {
                int rb = bRow8 + 8 * rr;
                cp_async16(sbase + b_soff(nxt, rb),
                           B + (long)(bk + TBK + rb) * HD + blockCol + bCol4);
            }
            asm volatile("cp.async.commit_group;" ::: "memory");
            asm volatile("cp.async.wait_group 1;" ::: "memory");
        } else {
            asm volatile("cp.async.wait_group 0;" ::: "memory");
        }
        __syncthreads();

        const float* Asb = smp + cur * VASZ;
        const float* Bsb = smp + 2 * VASZ + cur * BSZ;

        #pragma unroll
        for (int kk = 0; kk < TBK; kk += 8) {
            uint32_t ah[2][4], al[2][4];
            #pragma unroll
            for (int mi = 0; mi < 2; mi++) {
                int r0 = warpM * 32 + mi * 16 + grp;
                split_tf32(Asb[(r0    ) * ASTRIDE + kk + tig    ], ah[mi][0], al[mi][0]);
                split_tf32(Asb[(r0 + 8) * ASTRIDE + kk + tig    ], ah[mi][1], al[mi][1]);
                split_tf32(Asb[(r0    ) * ASTRIDE + kk + tig + 4], ah[mi][2], al[mi][2]);
                split_tf32(Asb[(r0 + 8) * ASTRIDE + kk + tig + 4], ah[mi][3], al[mi][3]);
            }
            uint32_t bh[4][2], bl[4][2];
            #pragma unroll
            for (int ni = 0; ni < 4; ni++) {
                int c0 = warpN * 32 + ni * 8 + grp;
                split_tf32(Bsb[(kk + tig    ) * BSTRIDE + c0], bh[ni][0], bl[ni][0]);
                split_tf32(Bsb[(kk + tig + 4) * BSTRIDE + c0], bh[ni][1], bl[ni][1]);
            }
            #pragma unroll
            for (int mi = 0; mi < 2; mi++)
                #pragma unroll
                for (int ni = 0; ni < 4; ni++) {
                    mma_tf32(acc[mi][ni], al[mi], bh[ni]);
                    mma_tf32(acc[mi][ni], ah[mi], bl[ni]);
                    mma_tf32(acc[mi][ni], ah[mi], bh[ni]);
                }
        }
        __syncthreads();
        cur ^= 1;
    }

    #pragma unroll
    for (int mi = 0; mi < 2; mi++) {
        int row = warpM * 32 + mi * 16 + grp;
        #pragma unroll
        for (int ni = 0; ni < 4; ni++) {
            int col = blockCol + warpN * 32 + ni * 8 + 2 * tig;
            *reinterpret_cast<float2*>(&C[(long)row * HD + col]) =
                make_float2(acc[mi][ni][0], acc[mi][ni][1]);
            *reinterpret_cast<float2*>(&C[(long)(row + 8) * HD + col]) =
                make_float2(acc[mi][ni][2], acc[mi][ni][3]);
        }
    }
}

// ---------------- proto mean + norm (fused) ----------------
__global__ void proto_pn_kernel(const float* __restrict__ t, float* __restrict__ proto,
                                float* __restrict__ pn) {
    int b = blockIdx.x, h = threadIdx.x;
    const float* tb = t + (long)b * NNODES * HD + h;
    float s = 0.f;
    #pragma unroll 4
    for (int n = 0; n < NNODES; n++) s += tb[(long)n * HD];
    float p = s * (1.0f / NNODES);
    proto[b * HD + h] = p;
    __shared__ float red[8];
    float sq = warp_sum(p * p);
    if ((h & 31) == 0) red[h >> 5] = sq;
    __syncthreads();
    if (h == 0) {
        float tot = 0.f;
        #pragma unroll
        for (int i = 0; i < 8; i++) tot += red[i];
        pn[b] = fmaxf(sqrtf(tot), 1e-8f);
    }
}

// ---------------- fused attention + row-normalized mw (writes TRANSPOSED c) ----------------
__global__ void att_mw_kernel(const float* __restrict__ t, const float* __restrict__ proto,
                              const float* __restrict__ pn, const float* __restrict__ ew,
                              float* __restrict__ ct) {
    int warp = (blockIdx.x * blockDim.x + threadIdx.x) >> 5;
    int lane = threadIdx.x & 31;
    if (warp >= TOTAL_N) return;
    int b  = warp >> 9;
    int nl = warp & 511;
    const float* tr = t + (long)warp * HD;
    const float* pr = proto + b * HD;
    float s2 = 0.f, dp = 0.f;
    #pragma unroll
    for (int h = lane; h < HD; h += 32) {
        float tv = tr[h];
        s2 += tv * tv;
        dp += tv * pr[h];
    }
    s2 = warp_sum(s2);
    dp = warp_sum(dp);
    float tn = fmaxf(sqrtf(s2), 1e-8f);
    float a  = 0.5f * (1.0f + dp / (tn * pn[b]));

    const float* er = ew + (long)warp * NV;
    float m0 = er[lane]      * a;
    float m1 = er[lane + 32] * a;
    float rs = warp_sum(m0 + m1);
    float d  = (rs == 0.f) ? 1.f : rs;
    ct[((long)b * NV + lane)      * NNODES + nl] = m0 / d;
    ct[((long)b * NV + lane + 32) * NNODES + nl] = m1 / d;
}

// ---------------- fused tail: gf mean + MLP1 + out ----------------
__global__ void tail_kernel(const float* __restrict__ vn2,
                            const float* __restrict__ mW1, const float* __restrict__ mb1,
                            const float* __restrict__ mW2, const float* __restrict__ mb2,
                            float* __restrict__ out) {
    int b = blockIdx.x, h = threadIdx.x;
    __shared__ float sgf[HD];
    __shared__ float sm1[HD];

    float s = 0.f;
    #pragma unroll 4
    for (int v = 0; v < NV; v++) s += vn2[((long)b * NV + v) * HD + h];
    sgf[h] = s * (1.0f / NV);
    __syncthreads();

    float acc = 0.f;
    #pragma unroll 4
    for (int k = 0; k < HD; k++) acc += sgf[k] * mW1[(long)k * HD + h];
    sm1[h] = fmaxf(acc + mb1[h], 0.f);
    __syncthreads();

    if (h < OUT_DIM) {
        float a2 = 0.f;
        #pragma unroll 4
        for (int k = 0; k < HD; k++) a2 += sm1[k] * mW2[(long)k * OUT_DIM + h];
        out[b * OUT_DIM + h] = a2 + mb2[h];
    }
}

// ---------------- launch ----------------
extern "C" void kernel_launch(void* const* d_in, const int* in_sizes, int n_in,
                              void* d_out, int out_size) {
    const float* x     = (const float*)d_in[0];
    const int*   esrc  = (const int*)  d_in[1];
    const int*   edst  = (const int*)  d_in[2];
    const float* W_emb = (const float*)d_in[3];
    const float* b_emb = (const float*)d_in[4];
    const float* W_gcn = (const float*)d_in[5];
    const float* b_gcn = (const float*)d_in[6];
    const float* aW1   = (const float*)d_in[7];
    const float* ab1   = (const float*)d_in[8];
    const float* aW2   = (const float*)d_in[9];
    const float* ab2   = (const float*)d_in[10];
    const float* vW1   = (const float*)d_in[11];
    const float* vb1   = (const float*)d_in[12];
    const float* vW2   = (const float*)d_in[13];
    const float* vb2   = (const float*)d_in[14];
    const float* mW1   = (const float*)d_in[15];
    const float* mb1   = (const float*)d_in[16];
    const float* mW2   = (const float*)d_in[17];
    const float* mb2   = (const float*)d_in[18];
    const float* ew    = (const float*)d_in[19];
    float* out = (float*)d_out;

    float *d_dinv, *d_wc, *d_bc, *d_y, *d_sc, *d_g, *d_t1, *d_t, *d_proto, *d_pn,
          *d_ct, *d_vn, *d_vnr, *d_vn2;
    int *d_cnt, *d_csr;
    cudaGetSymbolAddress((void**)&d_cnt,   g_cnt);
    cudaGetSymbolAddress((void**)&d_dinv,  g_dinv);
    cudaGetSymbolAddress((void**)&d_csr,   g_csr);
    cudaGetSymbolAddress((void**)&d_wc,    g_wc);
    cudaGetSymbolAddress((void**)&d_bc,    g_bc);
    cudaGetSymbolAddress((void**)&d_y,     g_y);
    cudaGetSymbolAddress((void**)&d_sc,    g_sc);
    cudaGetSymbolAddress((void**)&d_g,     g_g);
    cudaGetSymbolAddress((void**)&d_t1,    g_t1);
    cudaGetSymbolAddress((void**)&d_t,     g_t);
    cudaGetSymbolAddress((void**)&d_proto, g_proto);
    cudaGetSymbolAddress((void**)&d_pn,    g_pn);
    cudaGetSymbolAddress((void**)&d_ct,    g_ct);
    cudaGetSymbolAddress((void**)&d_vn,    g_vn);
    cudaGetSymbolAddress((void**)&d_vnr,   g_vnr);
    cudaGetSymbolAddress((void**)&d_vn2,   g_vn2);

    static int smem_set = 0;
    if (!smem_set) {
        cudaFuncSetAttribute(tf32x3_gemm_db,
                             cudaFuncAttributeMaxDynamicSharedMemorySize, GEMM_DB_SMEM);
        cudaFuncSetAttribute(vn_gemm_db,
                             cudaFuncAttributeMaxDynamicSharedMemorySize, VN_DB_SMEM);
        smem_set = 1;
    }

    // CSR build (counts double as degrees)
    cnt_zero_kernel<<<TOTAL_N / 256, 256>>>(d_cnt);
    csr_fill_kernel<<<EDGES / 256, 256>>>(esrc, edst, d_cnt, d_csr);
    dinv_kernel<<<TOTAL_N / 256, 256>>>(d_cnt, d_dinv);

    // weight fold (block-internal split-K)
    fold4_kernel<<<IN_DIM + 1, 1024>>>(W_emb, b_emb, W_gcn, d_wc, d_bc);

    // sparse aggregation in x-space (8-wide unroll)
    gcn_gather_x<<<TOTAL_N / 8, 256>>>(d_cnt, d_csr, d_dinv,
                                       (const float4*)x, (float4*)d_y, d_sc);

    // g = relu(y @ Wc + sc*bc + b_gcn)
    tf32x3_gemm_db<<<dim3(HD / TBN, TOTAL_N / TBM), 256, GEMM_DB_SMEM>>>(
        d_y, d_wc, b_gcn, d_g, TOTAL_N, HD, IN_DIM, 1, 1, d_sc, d_bc, 1);

    // affinity MLP
    tf32x3_gemm_db<<<dim3(HD / TBN, TOTAL_N / TBM), 256, GEMM_DB_SMEM>>>(
        d_g, aW1, ab1, d_t1, TOTAL_N, HD, HD, 1, 1, nullptr, nullptr, 0);
    tf32x3_gemm_db<<<dim3(HD / TBN, TOTAL_N / TBM), 256, GEMM_DB_SMEM>>>(
        d_t1, aW2, ab2, d_t, TOTAL_N, HD, HD, 1, 0, nullptr, nullptr, 0);

    proto_pn_kernel<<<NB, HD>>>(d_t, d_proto, d_pn);
    att_mw_kernel<<<TOTAL_N / 8, 256>>>(d_t, d_proto, d_pn, ew, d_ct);

    // vn[b] = ct[b] @ g[b]  (double-buffered)
    vn_gemm_db<<<dim3(HD / TBN, 1, NB), 256, VN_DB_SMEM>>>(d_ct, d_g, d_vn);

    // virtual-node MLP
    tf32x3_gemm_db<<<dim3(HD / TBN, (NB * NV) / TBM), 256, GEMM_DB_SMEM>>>(
        d_vn, vW1, vb1, d_vnr, NB * NV, HD, HD, 1, 1, nullptr, nullptr, 0);
    tf32x3_gemm_db<<<dim3(HD / TBN, (NB * NV) / TBM), 256, GEMM_DB_SMEM>>>(
        d_vnr, vW2, vb2, d_vn2, NB * NV, HD, HD, 1, 0, nullptr, nullptr, 0);

    // fused tail
    tail_kernel<<<NB, HD>>>(d_vn2, mW1, mb1, mW2, mb2, out);
}